// round 12
// baseline (speedup 1.0000x reference)
#include <cuda_runtime.h>
#include <cuda_bf16.h>
#include <mma.h>
#include <cstdint>

using namespace nvcuda;

#define NN 50000
#define EE 800000
#define CC 64
#define BN_EPS 1e-5f

#define NODE_BLOCKS 1563          // ceil(50000/32)
#define CONV_BLOCKS 3125          // 800000/256
#define STAT_BLOCKS 2048

// ---------------- scratch (static __device__ globals; no allocation) ----------------
static __device__ __align__(16) float g_P[NN * CC];      // x @ W0[:64]
static __device__ __align__(16) float g_Q[NN * CC];      // x @ W0[64:]
static __device__ __align__(16) float g_Y[EE * CC];      // sorted-order y2 scratch
static __device__ int   g_src[EE];
static __device__ int   g_dst[EE];
static __device__ int   g_ssrc[EE];                      // src of sorted edge
static __device__ int   g_sdst[EE];                      // dst of sorted edge
static __device__ int   g_deg[NN];
static __device__ int   g_off[NN + 1];
static __device__ int   g_cur[NN];
static __device__ int   g_eperm[EE];                     // sorted pos -> original edge id
static __device__ __align__(16) float g_sum[3][CC];
static __device__ __align__(16) float g_sq[3][CC];
static __device__ __align__(16) float g_bnA[3][CC];
static __device__ __align__(16) float g_bnB[3][CC];
static __device__ int   g_is64;
// bf16 hi/lo split of W1/W2 (row-major [k][n])
static __device__ __align__(16) __nv_bfloat16 g_Whi[2][4096];
static __device__ __align__(16) __nv_bfloat16 g_Wlo[2][4096];

// ---------------- smem layout for the layer kernels (bytes) ----------------
// stage (fp32, 128 x 68) is DISJOINT from A and B: no aliasing hazards.
#define LDA 72
#define LDB 72
#define LDS_F 68
#define O_STAGE 0
#define O_AHI   34816                  // 128*68*4
#define O_ALO   (O_AHI + 18432)        // 128*72*2
#define O_B     (O_ALO + 18432)
#define O_BHI   O_B
#define O_BLO   (O_B + 9216)           // 64*72*2
#define SMEM_LK (O_B + 18432)          // 90112

// ---------------- kernels ----------------

// zero scratch; block 0 detects int64 vs int32; blocks 1,2 do the W hi/lo split.
__global__ void k_zero(const unsigned* __restrict__ w,
                       const float* __restrict__ W1,
                       const float* __restrict__ W2) {
    int i = blockIdx.x * 256 + threadIdx.x;
    if (i < NN) g_deg[i] = 0;
    if (i < 3 * CC) {
        ((float*)g_sum)[i] = 0.0f;
        ((float*)g_sq)[i] = 0.0f;
    }
    if (blockIdx.x == 0) {
        __shared__ int bad;
        if (threadIdx.x == 0) bad = 0;
        __syncthreads();
        int b = 0;
        for (int j = threadIdx.x; j < 1024; j += 256)
            if (w[2 * j + 1] != 0u) b = 1;
        if (b) atomicOr(&bad, 1);
        __syncthreads();
        if (threadIdx.x == 0) g_is64 = bad ? 0 : 1;
    } else if (blockIdx.x <= 2) {
        int which = blockIdx.x - 1;
        const float* W = (which == 0) ? W1 : W2;
        for (int idx = threadIdx.x; idx < 4096; idx += 256) {
            float v = W[idx];
            __nv_bfloat16 hi = __float2bfloat16(v);
            __nv_bfloat16 lo = __float2bfloat16(v - __bfloat162float(hi));
            g_Whi[which][idx] = hi;
            g_Wlo[which][idx] = lo;
        }
    }
}

__global__ void k_convert(const void* __restrict__ ei) {
    int e = blockIdx.x * 256 + threadIdx.x;
    if (e >= EE) return;
    int s, d;
    if (g_is64) {
        const long long* p = (const long long*)ei;
        s = (int)p[e];
        d = (int)p[EE + e];
    } else {
        const int* p = (const int*)ei;
        s = p[e];
        d = p[EE + e];
    }
    g_src[e] = s;
    g_dst[e] = d;
    atomicAdd(&g_deg[d], 1);
}

// Node-level GEMM: P = x @ W0[:64], Q = x @ W0[64:].
// Extra block (== NODE_BLOCKS) runs the degree scan, hidden under the GEMM wave.
__global__ void __launch_bounds__(256) k_node(const float* __restrict__ x,
                                              const float* __restrict__ W0) {
    __shared__ float sW[64][128];
    __shared__ float sx[32][64];
    int t = threadIdx.x;

    if (blockIdx.x == NODE_BLOCKS) {
        __shared__ int part[256];
        const int CH = (NN + 255) / 256;   // 196
        int base = t * CH;
        int s = 0;
        for (int j = 0; j < CH; j++) {
            int n = base + j;
            if (n < NN) s += g_deg[n];
        }
        part[t] = s;
        __syncthreads();
        for (int off = 1; off < 256; off <<= 1) {
            int v = (t >= off) ? part[t - off] : 0;
            __syncthreads();
            part[t] += v;
            __syncthreads();
        }
        int run = part[t] - s;
        for (int j = 0; j < CH; j++) {
            int n = base + j;
            if (n < NN) {
                g_off[n] = run;
                g_cur[n] = run;
                run += g_deg[n];
            }
        }
        if (t == 255) g_off[NN] = EE;
        return;
    }

#pragma unroll
    for (int i = 0; i < 32; i++) {
        int idx = t + i * 256;
        int k = idx >> 7;
        int cc = idx & 127;
        sW[k][cc] = (cc < 64) ? W0[k * 64 + cc] : W0[(64 + k) * 64 + (cc - 64)];
    }
    int n0 = blockIdx.x * 32;
#pragma unroll
    for (int i = 0; i < 8; i++) {
        int idx = t + i * 256;
        int nl = idx >> 6;
        int k = idx & 63;
        int n = n0 + nl;
        sx[nl][k] = (n < NN) ? x[n * 64 + k] : 0.0f;
    }
    __syncthreads();
    int tc = t & 31;
    int tn = t >> 5;
    float acc[4][4] = {};
#pragma unroll 16
    for (int k = 0; k < 64; k++) {
        float4 w = *(const float4*)&sW[k][tc * 4];
        float x0 = sx[tn * 4 + 0][k];
        float x1 = sx[tn * 4 + 1][k];
        float x2 = sx[tn * 4 + 2][k];
        float x3 = sx[tn * 4 + 3][k];
        acc[0][0] = fmaf(x0, w.x, acc[0][0]); acc[0][1] = fmaf(x0, w.y, acc[0][1]);
        acc[0][2] = fmaf(x0, w.z, acc[0][2]); acc[0][3] = fmaf(x0, w.w, acc[0][3]);
        acc[1][0] = fmaf(x1, w.x, acc[1][0]); acc[1][1] = fmaf(x1, w.y, acc[1][1]);
        acc[1][2] = fmaf(x1, w.z, acc[1][2]); acc[1][3] = fmaf(x1, w.w, acc[1][3]);
        acc[2][0] = fmaf(x2, w.x, acc[2][0]); acc[2][1] = fmaf(x2, w.y, acc[2][1]);
        acc[2][2] = fmaf(x2, w.z, acc[2][2]); acc[2][3] = fmaf(x2, w.w, acc[2][3]);
        acc[3][0] = fmaf(x3, w.x, acc[3][0]); acc[3][1] = fmaf(x3, w.y, acc[3][1]);
        acc[3][2] = fmaf(x3, w.z, acc[3][2]); acc[3][3] = fmaf(x3, w.w, acc[3][3]);
    }
#pragma unroll
    for (int i = 0; i < 4; i++) {
        int n = n0 + tn * 4 + i;
        if (n < NN) {
            float4 v = make_float4(acc[i][0], acc[i][1], acc[i][2], acc[i][3]);
            if (tc < 16)
                *(float4*)&g_P[n * 64 + tc * 4] = v;
            else
                *(float4*)&g_Q[n * 64 + (tc - 16) * 4] = v;
        }
    }
}

// Merged: blocks [0, CONV_BLOCKS) do the counting-sort scatter; blocks
// [CONV_BLOCKS, +STAT_BLOCKS) do layer-0 BN stats over the unsorted pairs.
__global__ void k_sort_stats() {
    __shared__ float ss[CC], sq[CC];
    int t = threadIdx.x;
    int b = blockIdx.x;

    if (b < CONV_BLOCKS) {
        int e = b * 256 + t;
        if (e >= EE) return;
        int s = g_src[e];
        int d = g_dst[e];
        int pos = atomicAdd(&g_cur[d], 1);
        g_eperm[pos] = e;
        g_ssrc[pos] = s;
        g_sdst[pos] = d;
        return;
    }

    if (t < CC) { ss[t] = 0.0f; sq[t] = 0.0f; }
    __syncthreads();
    int lane = t & 31;
    int warp = ((b - CONV_BLOCKS) * 256 + t) >> 5;
    int nw = (STAT_BLOCKS * 256) >> 5;
    float2 s = make_float2(0.0f, 0.0f), q = make_float2(0.0f, 0.0f);
    for (int e = warp; e < EE; e += nw) {
        int dst = g_dst[e], src = g_src[e];
        float2 p = *(const float2*)&g_P[dst * CC + 2 * lane];
        float2 qq = *(const float2*)&g_Q[src * CC + 2 * lane];
        float y0 = p.x + qq.x, y1 = p.y + qq.y;
        s.x += y0; s.y += y1;
        q.x = fmaf(y0, y0, q.x); q.y = fmaf(y1, y1, q.y);
    }
    atomicAdd(&ss[2 * lane], s.x);
    atomicAdd(&ss[2 * lane + 1], s.y);
    atomicAdd(&sq[2 * lane], q.x);
    atomicAdd(&sq[2 * lane + 1], q.y);
    __syncthreads();
    if (t < CC) {
        atomicAdd(&g_sum[0][t], ss[t]);
        atomicAdd(&g_sq[0][t], sq[t]);
    }
}

__global__ void k_finalize(int layer, const float* __restrict__ gam,
                           const float* __restrict__ bet) {
    int c = threadIdx.x;
    float inv = 1.0f / (float)EE;
    float m = g_sum[layer][c] * inv;
    float v = g_sq[layer][c] * inv - m * m;
    float a = gam[c] * rsqrtf(v + BN_EPS);
    g_bnA[layer][c] = a;
    g_bnB[layer][c] = bet[c] - m * a;
}

// ---------------- shared device helpers for the layer kernels ----------------

__device__ __forceinline__ void load_W_smem(char* smem, int which, int t) {
    const uint32_t* wh = (const uint32_t*)&g_Whi[which][0];
    const uint32_t* wl = (const uint32_t*)&g_Wlo[which][0];
    __nv_bfloat16* B_hi = (__nv_bfloat16*)(smem + O_BHI);
    __nv_bfloat16* B_lo = (__nv_bfloat16*)(smem + O_BLO);
#pragma unroll
    for (int i = 0; i < 8; i++) {
        int idx2 = t + i * 256;          // pair index, 0..2047
        int k = idx2 >> 5, n2 = idx2 & 31;
        ((uint32_t*)(B_hi + k * LDB))[n2] = wh[idx2];
        ((uint32_t*)(B_lo + k * LDB))[n2] = wl[idx2];
    }
}

// BN+ReLU+bf16-split 8 values, write to A row r at col c.
__device__ __forceinline__ void bn_split_store(char* smem, int L, int r, int c,
                                               float4 a0, float4 a1) {
    __nv_bfloat16* A_hi = (__nv_bfloat16*)(smem + O_AHI);
    __nv_bfloat16* A_lo = (__nv_bfloat16*)(smem + O_ALO);
    float v[8] = {a0.x, a0.y, a0.z, a0.w, a1.x, a1.y, a1.z, a1.w};
    float4 A0 = *(const float4*)&g_bnA[L][c];
    float4 A1 = *(const float4*)&g_bnA[L][c + 4];
    float4 B0 = *(const float4*)&g_bnB[L][c];
    float4 B1 = *(const float4*)&g_bnB[L][c + 4];
    float bnA[8] = {A0.x, A0.y, A0.z, A0.w, A1.x, A1.y, A1.z, A1.w};
    float bnB[8] = {B0.x, B0.y, B0.z, B0.w, B1.x, B1.y, B1.z, B1.w};
    uint32_t hw[4], lw[4];
#pragma unroll
    for (int j = 0; j < 4; j++) {
        float x0 = fmaxf(fmaf(bnA[2 * j],     v[2 * j],     bnB[2 * j]),     0.0f);
        float x1 = fmaxf(fmaf(bnA[2 * j + 1], v[2 * j + 1], bnB[2 * j + 1]), 0.0f);
        __nv_bfloat16 h0 = __float2bfloat16(x0);
        __nv_bfloat16 h1 = __float2bfloat16(x1);
        __nv_bfloat16 l0 = __float2bfloat16(x0 - __bfloat162float(h0));
        __nv_bfloat16 l1 = __float2bfloat16(x1 - __bfloat162float(h1));
        hw[j] = (uint32_t)__bfloat16_as_ushort(h0) |
                ((uint32_t)__bfloat16_as_ushort(h1) << 16);
        lw[j] = (uint32_t)__bfloat16_as_ushort(l0) |
                ((uint32_t)__bfloat16_as_ushort(l1) << 16);
    }
    *(uint4*)&A_hi[r * LDA + c] = make_uint4(hw[0], hw[1], hw[2], hw[3]);
    *(uint4*)&A_lo[r * LDA + c] = make_uint4(lw[0], lw[1], lw[2], lw[3]);
}

// A-fill from P[sdst]+Q[ssrc] with BN0+ReLU. Thread = (row r, half).
__device__ __forceinline__ void fill_A_from_PQ(char* smem, int e0, int t) {
    int r = t >> 1, half = t & 1;
    int pos = e0 + r;
    const float* src0 = &g_P[(size_t)g_sdst[pos] * CC];
    const float* src1 = &g_Q[(size_t)g_ssrc[pos] * CC];
    int cbase = half * 32;
#pragma unroll
    for (int i = 0; i < 4; i++) {
        int c = cbase + i * 8;
        float4 a0 = *(const float4*)&src0[c];
        float4 a1 = *(const float4*)&src0[c + 4];
        float4 b0 = *(const float4*)&src1[c];
        float4 b1 = *(const float4*)&src1[c + 4];
        a0.x += b0.x; a0.y += b0.y; a0.z += b0.z; a0.w += b0.w;
        a1.x += b1.x; a1.y += b1.y; a1.z += b1.z; a1.w += b1.w;
        bn_split_store(smem, 0, r, c, a0, a1);
    }
}

// GEMM: y = Ahi*Bhi + Alo*Bhi + Ahi*Blo (fp32), result to stage (disjoint -> no sync).
__device__ __forceinline__ void do_gemm(char* smem, int t) {
    const __nv_bfloat16* A_hi = (const __nv_bfloat16*)(smem + O_AHI);
    const __nv_bfloat16* A_lo = (const __nv_bfloat16*)(smem + O_ALO);
    const __nv_bfloat16* B_hi = (const __nv_bfloat16*)(smem + O_BHI);
    const __nv_bfloat16* B_lo = (const __nv_bfloat16*)(smem + O_BLO);
    float* stage = (float*)(smem + O_STAGE);
    int w = t >> 5;
    int row0 = w * 16;
    wmma::fragment<wmma::accumulator, 16, 16, 16, float> acc[4];
#pragma unroll
    for (int j = 0; j < 4; j++) wmma::fill_fragment(acc[j], 0.0f);
#pragma unroll
    for (int k0 = 0; k0 < 64; k0 += 16) {
        wmma::fragment<wmma::matrix_a, 16, 16, 16, __nv_bfloat16, wmma::row_major> ah, al;
        wmma::load_matrix_sync(ah, A_hi + row0 * LDA + k0, LDA);
        wmma::load_matrix_sync(al, A_lo + row0 * LDA + k0, LDA);
#pragma unroll
        for (int j = 0; j < 4; j++) {
            wmma::fragment<wmma::matrix_b, 16, 16, 16, __nv_bfloat16, wmma::row_major> bh, bl;
            wmma::load_matrix_sync(bh, B_hi + k0 * LDB + j * 16, LDB);
            wmma::load_matrix_sync(bl, B_lo + k0 * LDB + j * 16, LDB);
            wmma::mma_sync(acc[j], ah, bh, acc[j]);
            wmma::mma_sync(acc[j], al, bh, acc[j]);
            wmma::mma_sync(acc[j], ah, bl, acc[j]);
        }
    }
#pragma unroll
    for (int j = 0; j < 4; j++)
        wmma::store_matrix_sync(stage + row0 * LDS_F + j * 16, acc[j], LDS_F,
                                wmma::mem_row_major);
}

// column stats over the 128x64 stage tile -> g_sum/g_sq[SL]
__device__ __forceinline__ void stage_stats(char* smem, int SL, int t) {
    const float* stage = (const float*)(smem + O_STAGE);
    int c = t & 63, quarter = t >> 6;
    float s = 0.0f, q = 0.0f;
#pragma unroll 8
    for (int rr = 0; rr < 32; rr++) {
        float vv = stage[(quarter * 32 + rr) * LDS_F + c];
        s += vv;
        q = fmaf(vv, vv, q);
    }
    atomicAdd(&g_sum[SL][c], s);
    atomicAdd(&g_sq[SL][c], q);
}

// Layer-1 stats pass: gather+BN0 -> GEMM W1 -> stats1. NO global store.
__global__ void __launch_bounds__(256) k_layer1s() {
    extern __shared__ char smem[];
    int t = threadIdx.x;
    load_W_smem(smem, 0, t);
    fill_A_from_PQ(smem, blockIdx.x * 128, t);
    __syncthreads();
    do_gemm(smem, t);
    __syncthreads();
    stage_stats(smem, 1, t);
}

// Layer-2 pass: recompute y1 (gather+BN0 -> GEMM W1), BN1+ReLU in smem,
// GEMM W2 -> y2 to g_Y + stats2.
__global__ void __launch_bounds__(256) k_layer2() {
    extern __shared__ char smem[];
    float* stage = (float*)(smem + O_STAGE);
    int t = threadIdx.x;
    int e0 = blockIdx.x * 128;

    load_W_smem(smem, 0, t);
    fill_A_from_PQ(smem, e0, t);
    __syncthreads();
    do_gemm(smem, t);                    // y1 -> stage
    __syncthreads();                     // stage done; A/B free

    load_W_smem(smem, 1, t);             // W2 -> B region
    {
        int r = t >> 1, half = t & 1;
        int cbase = half * 32;
#pragma unroll
        for (int i = 0; i < 4; i++) {
            int c = cbase + i * 8;
            float4 a0 = *(const float4*)&stage[r * LDS_F + c];
            float4 a1 = *(const float4*)&stage[r * LDS_F + c + 4];
            bn_split_store(smem, 1, r, c, a0, a1);
        }
    }
    __syncthreads();
    do_gemm(smem, t);                    // y2 -> stage
    __syncthreads();

    stage_stats(smem, 2, t);

    // coalesced store of the 128x64 y2 tile to sorted scratch
    float* dst = g_Y + (size_t)e0 * CC;
#pragma unroll
    for (int j2 = 0; j2 < 8; j2++) {
        int f = j2 * 1024 + t * 4;
        int rr = f >> 6, cc2 = f & 63;
        uint4 v = *(const uint4*)&stage[rr * LDS_F + cc2];
        *(uint4*)&dst[f] = v;
    }
}

// Segmented mean: warp per node. Streams its CONTIGUOUS sorted g_Y segment,
// applies BN2+ReLU, scatter-writes edge rows to outE in original order,
// accumulates and writes the node mean. No atomics.
__global__ void __launch_bounds__(256) k_agg(float* __restrict__ out) {
    int wid = (blockIdx.x * 256 + threadIdx.x) >> 5;
    int lane = threadIdx.x & 31;
    if (wid >= NN) return;
    int start = g_off[wid], end = g_off[wid + 1];
    float2 A = *(const float2*)&g_bnA[2][lane * 2];
    float2 Bv = *(const float2*)&g_bnB[2][lane * 2];
    float2 acc = make_float2(0.0f, 0.0f);
    float* oe = out + (size_t)NN * CC;
#pragma unroll 2
    for (int j = start; j < end; j++) {
        float2 v = *(const float2*)&g_Y[(size_t)j * CC + lane * 2];
        v.x = fmaxf(fmaf(A.x, v.x, Bv.x), 0.0f);
        v.y = fmaxf(fmaf(A.y, v.y, Bv.y), 0.0f);
        int eid = g_eperm[j];
        *(float2*)&oe[(size_t)eid * CC + lane * 2] = v;
        acc.x += v.x;
        acc.y += v.y;
    }
    float d = fmaxf((float)(end - start), 1.0f);
    *(float2*)&out[(size_t)wid * CC + lane * 2] =
        make_float2(acc.x / d, acc.y / d);
}

extern "C" void kernel_launch(void* const* d_in, const int* in_sizes, int n_in,
                              void* d_out, int out_size) {
    const float* x = (const float*)d_in[0];
    const void* ei = d_in[1];
    const float* W0 = (const float*)d_in[2];
    const float* g0 = (const float*)d_in[4];
    const float* be0 = (const float*)d_in[5];
    const float* W1 = (const float*)d_in[6];
    const float* g1 = (const float*)d_in[8];
    const float* be1 = (const float*)d_in[9];
    const float* W2 = (const float*)d_in[10];
    const float* g2 = (const float*)d_in[12];
    const float* be2 = (const float*)d_in[13];
    float* out = (float*)d_out;

    static int s_attr_done = 0;
    if (!s_attr_done) {
        cudaFuncSetAttribute(k_layer1s, cudaFuncAttributeMaxDynamicSharedMemorySize, SMEM_LK);
        cudaFuncSetAttribute(k_layer2, cudaFuncAttributeMaxDynamicSharedMemorySize, SMEM_LK);
        s_attr_done = 1;
    }

    k_zero<<<(NN + 255) / 256, 256>>>((const unsigned*)ei, W1, W2);
    k_convert<<<CONV_BLOCKS, 256>>>(ei);
    k_node<<<NODE_BLOCKS + 1, 256>>>(x, W0);
    k_sort_stats<<<CONV_BLOCKS + STAT_BLOCKS, 256>>>();
    k_finalize<<<1, 64>>>(0, g0, be0);
    k_layer1s<<<EE / 128, 256, SMEM_LK>>>();
    k_finalize<<<1, 64>>>(1, g1, be1);
    k_layer2<<<EE / 128, 256, SMEM_LK>>>();
    k_finalize<<<1, 64>>>(2, g2, be2);
    k_agg<<<(NN * 32 + 255) / 256, 256>>>(out);
}

// round 13
// speedup vs baseline: 1.2004x; 1.2004x over previous
#include <cuda_runtime.h>
#include <cuda_bf16.h>
#include <mma.h>
#include <cstdint>

using namespace nvcuda;

#define NN 50000
#define EE 800000
#define CC 64
#define BN_EPS 1e-5f

// ---------------- scratch (static __device__ globals; no allocation) ----------------
static __device__ __align__(16) float g_P[NN * CC];      // x @ W0[:64]
static __device__ __align__(16) float g_Q[NN * CC];      // x @ W0[64:]
static __device__ __align__(16) float g_Y[EE * CC];      // sorted-order y scratch
static __device__ int   g_src[EE];
static __device__ int   g_dst[EE];
static __device__ int   g_ssrc[EE];                      // src of sorted edge
static __device__ int   g_sdst[EE];                      // dst of sorted edge
static __device__ int   g_deg[NN];
static __device__ int   g_off[NN + 1];
static __device__ int   g_cur[NN];
static __device__ int   g_eperm[EE];                     // sorted pos -> original edge id
static __device__ __align__(16) float g_sum[3][CC];
static __device__ __align__(16) float g_sq[3][CC];
static __device__ __align__(16) float g_bnA[3][CC];
static __device__ __align__(16) float g_bnB[3][CC];
static __device__ int   g_is64;
// bf16 hi/lo split of W1/W2 (row-major [k][n])
static __device__ __align__(16) __nv_bfloat16 g_Whi[2][4096];
static __device__ __align__(16) __nv_bfloat16 g_Wlo[2][4096];

// ---------------- smem layout for wmma layer kernel (bytes) ----------------
#define LDA 72          // bf16 elements per A row (padded)
#define LDB 72          // bf16 elements per B row (padded)
#define LDS_F 68        // fp32 elements per stage row (padded)
#define O_AHI 0
#define O_ALO 18432     // 128*72*2
#define O_BHI 36864
#define O_BLO 46080     // +64*72*2
#define SMEM_LK 55296

// ---------------- prologue kernels ----------------

__global__ void k_zero() {
    int i = blockIdx.x * 256 + threadIdx.x;
    if (i < NN) g_deg[i] = 0;
    if (i < 3 * CC) {
        ((float*)g_sum)[i] = 0.0f;
        ((float*)g_sq)[i] = 0.0f;
    }
}

__global__ void k_detect(const unsigned* __restrict__ w) {
    __shared__ int bad;
    if (threadIdx.x == 0) bad = 0;
    __syncthreads();
    int b = 0;
    for (int i = threadIdx.x; i < 1024; i += 256)
        if (w[2 * i + 1] != 0u) b = 1;
    if (b) atomicOr(&bad, 1);
    __syncthreads();
    if (threadIdx.x == 0) g_is64 = bad ? 0 : 1;
}

__global__ void k_convert(const void* __restrict__ ei) {
    int e = blockIdx.x * 256 + threadIdx.x;
    if (e >= EE) return;
    int s, d;
    if (g_is64) {
        const long long* p = (const long long*)ei;
        s = (int)p[e];
        d = (int)p[EE + e];
    } else {
        const int* p = (const int*)ei;
        s = p[e];
        d = p[EE + e];
    }
    g_src[e] = s;
    g_dst[e] = d;
    atomicAdd(&g_deg[d], 1);
}

// Node-level GEMM: P = x @ W0[:64], Q = x @ W0[64:].
__global__ void __launch_bounds__(256) k_node(const float* __restrict__ x,
                                              const float* __restrict__ W0) {
    __shared__ float sW[64][128];
    __shared__ float sx[32][64];
    int t = threadIdx.x;
#pragma unroll
    for (int i = 0; i < 32; i++) {
        int idx = t + i * 256;
        int k = idx >> 7;
        int cc = idx & 127;
        sW[k][cc] = (cc < 64) ? W0[k * 64 + cc] : W0[(64 + k) * 64 + (cc - 64)];
    }
    int n0 = blockIdx.x * 32;
#pragma unroll
    for (int i = 0; i < 8; i++) {
        int idx = t + i * 256;
        int nl = idx >> 6;
        int k = idx & 63;
        int n = n0 + nl;
        sx[nl][k] = (n < NN) ? x[n * 64 + k] : 0.0f;
    }
    __syncthreads();
    int tc = t & 31;
    int tn = t >> 5;
    float acc[4][4] = {};
#pragma unroll 16
    for (int k = 0; k < 64; k++) {
        float4 w = *(const float4*)&sW[k][tc * 4];
        float x0 = sx[tn * 4 + 0][k];
        float x1 = sx[tn * 4 + 1][k];
        float x2 = sx[tn * 4 + 2][k];
        float x3 = sx[tn * 4 + 3][k];
        acc[0][0] = fmaf(x0, w.x, acc[0][0]); acc[0][1] = fmaf(x0, w.y, acc[0][1]);
        acc[0][2] = fmaf(x0, w.z, acc[0][2]); acc[0][3] = fmaf(x0, w.w, acc[0][3]);
        acc[1][0] = fmaf(x1, w.x, acc[1][0]); acc[1][1] = fmaf(x1, w.y, acc[1][1]);
        acc[1][2] = fmaf(x1, w.z, acc[1][2]); acc[1][3] = fmaf(x1, w.w, acc[1][3]);
        acc[2][0] = fmaf(x2, w.x, acc[2][0]); acc[2][1] = fmaf(x2, w.y, acc[2][1]);
        acc[2][2] = fmaf(x2, w.z, acc[2][2]); acc[2][3] = fmaf(x2, w.w, acc[2][3]);
        acc[3][0] = fmaf(x3, w.x, acc[3][0]); acc[3][1] = fmaf(x3, w.y, acc[3][1]);
        acc[3][2] = fmaf(x3, w.z, acc[3][2]); acc[3][3] = fmaf(x3, w.w, acc[3][3]);
    }
#pragma unroll
    for (int i = 0; i < 4; i++) {
        int n = n0 + tn * 4 + i;
        if (n < NN) {
            float4 v = make_float4(acc[i][0], acc[i][1], acc[i][2], acc[i][3]);
            if (tc < 16)
                *(float4*)&g_P[n * 64 + tc * 4] = v;
            else
                *(float4*)&g_Q[n * 64 + (tc - 16) * 4] = v;
        }
    }
}

// single-block scan over degrees -> segment offsets (+ cursor copies)
__global__ void k_scan() {
    __shared__ int part[1024];
    int t = threadIdx.x;
    const int CH = (NN + 1023) / 1024;   // 49
    int base = t * CH;
    int s = 0;
    for (int j = 0; j < CH; j++) {
        int n = base + j;
        if (n < NN) s += g_deg[n];
    }
    part[t] = s;
    __syncthreads();
    for (int off = 1; off < 1024; off <<= 1) {
        int v = (t >= off) ? part[t - off] : 0;
        __syncthreads();
        part[t] += v;
        __syncthreads();
    }
    int run = part[t] - s;   // exclusive prefix for this chunk
    for (int j = 0; j < CH; j++) {
        int n = base + j;
        if (n < NN) {
            g_off[n] = run;
            g_cur[n] = run;
            run += g_deg[n];
        }
    }
    if (t == 1023) g_off[NN] = EE;
}

__global__ void k_sortE() {
    int e = blockIdx.x * 256 + threadIdx.x;
    if (e >= EE) return;
    int s = g_src[e];
    int d = g_dst[e];
    int pos = atomicAdd(&g_cur[d], 1);
    g_eperm[pos] = e;
    g_ssrc[pos] = s;
    g_sdst[pos] = d;
}

// Layer-0 stats over sorted pairs (dst-sorted -> P rows L1-resident).
__global__ void k_stats0() {
    __shared__ float ss[CC], sq[CC];
    int t = threadIdx.x;
    if (t < CC) { ss[t] = 0.0f; sq[t] = 0.0f; }
    __syncthreads();
    int lane = t & 31;
    int warp = (blockIdx.x * 256 + t) >> 5;
    int nw = (gridDim.x * 256) >> 5;
    float2 s = make_float2(0.0f, 0.0f), q = make_float2(0.0f, 0.0f);
    for (int e = warp; e < EE; e += nw) {
        int dst = g_sdst[e], src = g_ssrc[e];
        float2 p = *(const float2*)&g_P[dst * CC + 2 * lane];
        float2 qq = *(const float2*)&g_Q[src * CC + 2 * lane];
        float y0 = p.x + qq.x, y1 = p.y + qq.y;
        s.x += y0; s.y += y1;
        q.x = fmaf(y0, y0, q.x); q.y = fmaf(y1, y1, q.y);
    }
    atomicAdd(&ss[2 * lane], s.x);
    atomicAdd(&ss[2 * lane + 1], s.y);
    atomicAdd(&sq[2 * lane], q.x);
    atomicAdd(&sq[2 * lane + 1], q.y);
    __syncthreads();
    if (t < CC) {
        atomicAdd(&g_sum[0][t], ss[t]);
        atomicAdd(&g_sq[0][t], sq[t]);
    }
}

__global__ void k_finalize(int layer, const float* __restrict__ gam,
                           const float* __restrict__ bet) {
    int c = threadIdx.x;
    float inv = 1.0f / (float)EE;
    float m = g_sum[layer][c] * inv;
    float v = g_sq[layer][c] * inv - m * m;
    float a = gam[c] * rsqrtf(v + BN_EPS);
    g_bnA[layer][c] = a;
    g_bnB[layer][c] = bet[c] - m * a;
}

// Prologue: bf16 hi/lo split of W1, W2 (row-major [k][n]).
__global__ void k_prepW(const float* __restrict__ W1, const float* __restrict__ W2) {
    const float* W = (blockIdx.x == 0) ? W1 : W2;
    for (int idx = threadIdx.x; idx < 4096; idx += 256) {
        float x = W[idx];
        __nv_bfloat16 hi = __float2bfloat16(x);
        __nv_bfloat16 lo = __float2bfloat16(x - __bfloat162float(hi));
        g_Whi[blockIdx.x][idx] = hi;
        g_Wlo[blockIdx.x][idx] = lo;
    }
}

// ---------------- WMMA edge layer, sorted-position order ----------------
// mode 0: A = BN0+ReLU(P[sdst]+Q[ssrc]), B = W1, g_Y[pos] = y1, stats -> 1
// mode 1: A = BN1+ReLU(g_Y[pos]),        B = W2, g_Y[pos] = y2, stats -> 2
// y = Ahi*Bhi + Alo*Bhi + Ahi*Blo (fp32 accum).
// __launch_bounds__(256, 3): cap regs (~85) so 3 blocks/SM fit -> better
// latency hiding of the phase chain (this kernel is serialization-bound).
__global__ void __launch_bounds__(256, 3) k_layerT(int mode) {
    extern __shared__ char smem[];
    __nv_bfloat16* A_hi = (__nv_bfloat16*)(smem + O_AHI);
    __nv_bfloat16* A_lo = (__nv_bfloat16*)(smem + O_ALO);
    __nv_bfloat16* B_hi = (__nv_bfloat16*)(smem + O_BHI);
    __nv_bfloat16* B_lo = (__nv_bfloat16*)(smem + O_BLO);
    float* stage = (float*)smem;   // reuses A region after compute
    int t = threadIdx.x;

    // Prefetch gather indices FIRST: starts the dependent index->row chain
    // ~500 cycles before the W copy saturates the LSU.
    int e0 = blockIdx.x * 128;
    int r = t >> 1, half = t & 1;
    int pos = e0 + r;
    const float* src0;
    const float* src1 = nullptr;
    int L;
    if (mode == 0) {
        int nd = g_sdst[pos];
        int ns = g_ssrc[pos];
        src0 = &g_P[(size_t)nd * CC];
        src1 = &g_Q[(size_t)ns * CC];
        L = 0;
    } else {
        src0 = &g_Y[(size_t)pos * CC];
        L = 1;
    }

    // copy W hi/lo into padded smem (row k -> B[k*LDB .. +64))
    {
        const uint32_t* wh = (const uint32_t*)&g_Whi[mode][0];
        const uint32_t* wl = (const uint32_t*)&g_Wlo[mode][0];
#pragma unroll
        for (int i = 0; i < 8; i++) {
            int idx2 = t + i * 256;          // pair index, 0..2047
            int k = idx2 >> 5, n2 = idx2 & 31;
            ((uint32_t*)(B_hi + k * LDB))[n2] = wh[idx2];
            ((uint32_t*)(B_lo + k * LDB))[n2] = wl[idx2];
        }
    }

    // A fill: 2 threads per sorted row (32 cols each), BN+ReLU+split -> bf16 hi/lo
    int cbase = half * 32;
#pragma unroll
    for (int i = 0; i < 4; i++) {
        int c = cbase + i * 8;
        float4 a0 = *(const float4*)&src0[c];
        float4 a1 = *(const float4*)&src0[c + 4];
        if (mode == 0) {
            float4 b0 = *(const float4*)&src1[c];
            float4 b1 = *(const float4*)&src1[c + 4];
            a0.x += b0.x; a0.y += b0.y; a0.z += b0.z; a0.w += b0.w;
            a1.x += b1.x; a1.y += b1.y; a1.z += b1.z; a1.w += b1.w;
        }
        float v[8] = {a0.x, a0.y, a0.z, a0.w, a1.x, a1.y, a1.z, a1.w};
        float4 A0 = *(const float4*)&g_bnA[L][c];
        float4 A1 = *(const float4*)&g_bnA[L][c + 4];
        float4 B0 = *(const float4*)&g_bnB[L][c];
        float4 B1 = *(const float4*)&g_bnB[L][c + 4];
        float bnA[8] = {A0.x, A0.y, A0.z, A0.w, A1.x, A1.y, A1.z, A1.w};
        float bnB[8] = {B0.x, B0.y, B0.z, B0.w, B1.x, B1.y, B1.z, B1.w};
        uint32_t hw[4], lw[4];
#pragma unroll
        for (int j = 0; j < 4; j++) {
            float x0 = fmaxf(fmaf(bnA[2 * j],     v[2 * j],     bnB[2 * j]),     0.0f);
            float x1 = fmaxf(fmaf(bnA[2 * j + 1], v[2 * j + 1], bnB[2 * j + 1]), 0.0f);
            __nv_bfloat16 h0 = __float2bfloat16(x0);
            __nv_bfloat16 h1 = __float2bfloat16(x1);
            __nv_bfloat16 l0 = __float2bfloat16(x0 - __bfloat162float(h0));
            __nv_bfloat16 l1 = __float2bfloat16(x1 - __bfloat162float(h1));
            hw[j] = (uint32_t)__bfloat16_as_ushort(h0) |
                    ((uint32_t)__bfloat16_as_ushort(h1) << 16);
            lw[j] = (uint32_t)__bfloat16_as_ushort(l0) |
                    ((uint32_t)__bfloat16_as_ushort(l1) << 16);
        }
        *(uint4*)&A_hi[r * LDA + c] = make_uint4(hw[0], hw[1], hw[2], hw[3]);
        *(uint4*)&A_lo[r * LDA + c] = make_uint4(lw[0], lw[1], lw[2], lw[3]);
    }
    __syncthreads();

    // WMMA: warp w -> rows [w*16, w*16+16), all 64 cols
    int w = t >> 5;
    int row0 = w * 16;
    wmma::fragment<wmma::accumulator, 16, 16, 16, float> acc[4];
#pragma unroll
    for (int j = 0; j < 4; j++) wmma::fill_fragment(acc[j], 0.0f);
#pragma unroll
    for (int k0 = 0; k0 < 64; k0 += 16) {
        wmma::fragment<wmma::matrix_a, 16, 16, 16, __nv_bfloat16, wmma::row_major> ah, al;
        wmma::load_matrix_sync(ah, A_hi + row0 * LDA + k0, LDA);
        wmma::load_matrix_sync(al, A_lo + row0 * LDA + k0, LDA);
#pragma unroll
        for (int j = 0; j < 4; j++) {
            wmma::fragment<wmma::matrix_b, 16, 16, 16, __nv_bfloat16, wmma::row_major> bh, bl;
            wmma::load_matrix_sync(bh, B_hi + k0 * LDB + j * 16, LDB);
            wmma::load_matrix_sync(bl, B_lo + k0 * LDB + j * 16, LDB);
            wmma::mma_sync(acc[j], ah, bh, acc[j]);
            wmma::mma_sync(acc[j], al, bh, acc[j]);
            wmma::mma_sync(acc[j], ah, bl, acc[j]);
        }
    }
    __syncthreads();   // everyone done reading A region before stage overwrite
#pragma unroll
    for (int j = 0; j < 4; j++)
        wmma::store_matrix_sync(stage + row0 * LDS_F + j * 16, acc[j], LDS_F,
                                wmma::mem_row_major);
    __syncthreads();

    // column stats: 256 threads, c = t&63, quarter sums 32 rows
    int SL = (mode == 0) ? 1 : 2;
    {
        int c = t & 63, quarter = t >> 6;
        float s = 0.0f, q = 0.0f;
#pragma unroll 8
        for (int rr = 0; rr < 32; rr++) {
            float vv = stage[(quarter * 32 + rr) * LDS_F + c];
            s += vv;
            q = fmaf(vv, vv, q);
        }
        atomicAdd(&g_sum[SL][c], s);
        atomicAdd(&g_sq[SL][c], q);
    }

    // coalesced store of the 128x64 tile back to sorted scratch
    float* dst = g_Y + (size_t)e0 * CC;
#pragma unroll
    for (int j2 = 0; j2 < 8; j2++) {
        int f = j2 * 1024 + t * 4;
        int rr = f >> 6, cc2 = f & 63;
        uint4 v = *(const uint4*)&stage[rr * LDS_F + cc2];
        *(uint4*)&dst[f] = v;
    }
}

// Segmented mean: warp per node. Streams its CONTIGUOUS sorted g_Y segment
// (coalesced reads), applies BN2+ReLU, scatter-writes edge rows to outE in
// original order, accumulates and writes the node mean. No atomics.
__global__ void __launch_bounds__(256) k_agg(float* __restrict__ out) {
    int wid = (blockIdx.x * 256 + threadIdx.x) >> 5;
    int lane = threadIdx.x & 31;
    if (wid >= NN) return;
    int start = g_off[wid], end = g_off[wid + 1];
    float2 A = *(const float2*)&g_bnA[2][lane * 2];
    float2 Bv = *(const float2*)&g_bnB[2][lane * 2];
    float2 acc = make_float2(0.0f, 0.0f);
    float* oe = out + (size_t)NN * CC;
#pragma unroll 2
    for (int j = start; j < end; j++) {
        float2 v = *(const float2*)&g_Y[(size_t)j * CC + lane * 2];
        v.x = fmaxf(fmaf(A.x, v.x, Bv.x), 0.0f);
        v.y = fmaxf(fmaf(A.y, v.y, Bv.y), 0.0f);
        int eid = g_eperm[j];
        *(float2*)&oe[(size_t)eid * CC + lane * 2] = v;
        acc.x += v.x;
        acc.y += v.y;
    }
    float d = fmaxf((float)(end - start), 1.0f);
    *(float2*)&out[(size_t)wid * CC + lane * 2] =
        make_float2(acc.x / d, acc.y / d);
}

extern "C" void kernel_launch(void* const* d_in, const int* in_sizes, int n_in,
                              void* d_out, int out_size) {
    const float* x = (const float*)d_in[0];
    const void* ei = d_in[1];
    const float* W0 = (const float*)d_in[2];
    const float* g0 = (const float*)d_in[4];
    const float* be0 = (const float*)d_in[5];
    const float* W1 = (const float*)d_in[6];
    const float* g1 = (const float*)d_in[8];
    const float* be1 = (const float*)d_in[9];
    const float* W2 = (const float*)d_in[10];
    const float* g2 = (const float*)d_in[12];
    const float* be2 = (const float*)d_in[13];
    float* out = (float*)d_out;

    static int s_attr_done = 0;
    if (!s_attr_done) {
        cudaFuncSetAttribute(k_layerT, cudaFuncAttributeMaxDynamicSharedMemorySize, SMEM_LK);
        s_attr_done = 1;
    }

    k_zero<<<(NN + 255) / 256, 256>>>();
    k_detect<<<1, 256>>>((const unsigned*)ei);
    k_convert<<<(EE + 255) / 256, 256>>>(ei);
    k_node<<<(NN + 31) / 32, 256>>>(x, W0);
    k_scan<<<1, 1024>>>();
    k_sortE<<<(EE + 255) / 256, 256>>>();
    k_prepW<<<2, 256>>>(W1, W2);
    k_stats0<<<2048, 256>>>();
    k_finalize<<<1, 64>>>(0, g0, be0);
    k_layerT<<<EE / 128, 256, SMEM_LK>>>(0);
    k_finalize<<<1, 64>>>(1, g1, be1);
    k_layerT<<<EE / 128, 256, SMEM_LK>>>(1);
    k_finalize<<<1, 64>>>(2, g2, be2);
    k_agg<<<(NN * 32 + 255) / 256, 256>>>(out);
}

// round 14
// speedup vs baseline: 1.2654x; 1.0541x over previous
#include <cuda_runtime.h>
#include <cuda_bf16.h>
#include <mma.h>
#include <cstdint>

using namespace nvcuda;

#define NN 50000
#define EE 800000
#define CC 64
#define BN_EPS 1e-5f

// ---------------- scratch (static __device__ globals; no allocation) ----------------
static __device__ __align__(16) float g_P[NN * CC];      // x @ W0[:64]
static __device__ __align__(16) float g_Q[NN * CC];      // x @ W0[64:]
static __device__ __align__(16) float g_Y[EE * CC];      // sorted-order y scratch
static __device__ int   g_src[EE];
static __device__ int   g_dst[EE];
static __device__ int   g_ssrc[EE];                      // src of sorted edge
static __device__ int   g_sdst[EE];                      // dst of sorted edge
static __device__ int   g_deg[NN];
static __device__ int   g_off[NN + 1];
static __device__ int   g_cur[NN];
static __device__ int   g_eperm[EE];                     // sorted pos -> original edge id
static __device__ __align__(16) float g_sum[3][CC];
static __device__ __align__(16) float g_sq[3][CC];
static __device__ __align__(16) float g_bnA[3][CC];
static __device__ __align__(16) float g_bnB[3][CC];
static __device__ int   g_is64;
// bf16 hi/lo split of W1/W2 (row-major [k][n])
static __device__ __align__(16) __nv_bfloat16 g_Whi[2][4096];
static __device__ __align__(16) __nv_bfloat16 g_Wlo[2][4096];

// ---------------- smem layout for wmma layer kernel (bytes) ----------------
// 256-edge tile: A_hi/A_lo 256x72 bf16, B_hi/B_lo 64x72 bf16.
// fp32 stage (256x68) aliases the A region after the GEMM barrier.
#define ROWS 256
#define LDA 72
#define LDB 72
#define LDS_F 68
#define O_AHI 0
#define O_ALO 36864     // 256*72*2
#define O_BHI 73728
#define O_BLO 82944
#define SMEM_LK 92160

// ---------------- prologue kernels ----------------

__global__ void k_zero() {
    int i = blockIdx.x * 256 + threadIdx.x;
    if (i < NN) g_deg[i] = 0;
    if (i < 3 * CC) {
        ((float*)g_sum)[i] = 0.0f;
        ((float*)g_sq)[i] = 0.0f;
    }
}

__global__ void k_detect(const unsigned* __restrict__ w) {
    __shared__ int bad;
    if (threadIdx.x == 0) bad = 0;
    __syncthreads();
    int b = 0;
    for (int i = threadIdx.x; i < 1024; i += 256)
        if (w[2 * i + 1] != 0u) b = 1;
    if (b) atomicOr(&bad, 1);
    __syncthreads();
    if (threadIdx.x == 0) g_is64 = bad ? 0 : 1;
}

__global__ void k_convert(const void* __restrict__ ei) {
    int e = blockIdx.x * 256 + threadIdx.x;
    if (e >= EE) return;
    int s, d;
    if (g_is64) {
        const long long* p = (const long long*)ei;
        s = (int)p[e];
        d = (int)p[EE + e];
    } else {
        const int* p = (const int*)ei;
        s = p[e];
        d = p[EE + e];
    }
    g_src[e] = s;
    g_dst[e] = d;
    atomicAdd(&g_deg[d], 1);
}

// Node-level GEMM: P = x @ W0[:64], Q = x @ W0[64:].
__global__ void __launch_bounds__(256) k_node(const float* __restrict__ x,
                                              const float* __restrict__ W0) {
    __shared__ float sW[64][128];
    __shared__ float sx[32][64];
    int t = threadIdx.x;
#pragma unroll
    for (int i = 0; i < 32; i++) {
        int idx = t + i * 256;
        int k = idx >> 7;
        int cc = idx & 127;
        sW[k][cc] = (cc < 64) ? W0[k * 64 + cc] : W0[(64 + k) * 64 + (cc - 64)];
    }
    int n0 = blockIdx.x * 32;
#pragma unroll
    for (int i = 0; i < 8; i++) {
        int idx = t + i * 256;
        int nl = idx >> 6;
        int k = idx & 63;
        int n = n0 + nl;
        sx[nl][k] = (n < NN) ? x[n * 64 + k] : 0.0f;
    }
    __syncthreads();
    int tc = t & 31;
    int tn = t >> 5;
    float acc[4][4] = {};
#pragma unroll 16
    for (int k = 0; k < 64; k++) {
        float4 w = *(const float4*)&sW[k][tc * 4];
        float x0 = sx[tn * 4 + 0][k];
        float x1 = sx[tn * 4 + 1][k];
        float x2 = sx[tn * 4 + 2][k];
        float x3 = sx[tn * 4 + 3][k];
        acc[0][0] = fmaf(x0, w.x, acc[0][0]); acc[0][1] = fmaf(x0, w.y, acc[0][1]);
        acc[0][2] = fmaf(x0, w.z, acc[0][2]); acc[0][3] = fmaf(x0, w.w, acc[0][3]);
        acc[1][0] = fmaf(x1, w.x, acc[1][0]); acc[1][1] = fmaf(x1, w.y, acc[1][1]);
        acc[1][2] = fmaf(x1, w.z, acc[1][2]); acc[1][3] = fmaf(x1, w.w, acc[1][3]);
        acc[2][0] = fmaf(x2, w.x, acc[2][0]); acc[2][1] = fmaf(x2, w.y, acc[2][1]);
        acc[2][2] = fmaf(x2, w.z, acc[2][2]); acc[2][3] = fmaf(x2, w.w, acc[2][3]);
        acc[3][0] = fmaf(x3, w.x, acc[3][0]); acc[3][1] = fmaf(x3, w.y, acc[3][1]);
        acc[3][2] = fmaf(x3, w.z, acc[3][2]); acc[3][3] = fmaf(x3, w.w, acc[3][3]);
    }
#pragma unroll
    for (int i = 0; i < 4; i++) {
        int n = n0 + tn * 4 + i;
        if (n < NN) {
            float4 v = make_float4(acc[i][0], acc[i][1], acc[i][2], acc[i][3]);
            if (tc < 16)
                *(float4*)&g_P[n * 64 + tc * 4] = v;
            else
                *(float4*)&g_Q[n * 64 + (tc - 16) * 4] = v;
        }
    }
}

// single-block scan over degrees -> segment offsets (+ cursor copies)
__global__ void k_scan() {
    __shared__ int part[1024];
    int t = threadIdx.x;
    const int CH = (NN + 1023) / 1024;   // 49
    int base = t * CH;
    int s = 0;
    for (int j = 0; j < CH; j++) {
        int n = base + j;
        if (n < NN) s += g_deg[n];
    }
    part[t] = s;
    __syncthreads();
    for (int off = 1; off < 1024; off <<= 1) {
        int v = (t >= off) ? part[t - off] : 0;
        __syncthreads();
        part[t] += v;
        __syncthreads();
    }
    int run = part[t] - s;   // exclusive prefix for this chunk
    for (int j = 0; j < CH; j++) {
        int n = base + j;
        if (n < NN) {
            g_off[n] = run;
            g_cur[n] = run;
            run += g_deg[n];
        }
    }
    if (t == 1023) g_off[NN] = EE;
}

__global__ void k_sortE() {
    int e = blockIdx.x * 256 + threadIdx.x;
    if (e >= EE) return;
    int s = g_src[e];
    int d = g_dst[e];
    int pos = atomicAdd(&g_cur[d], 1);
    g_eperm[pos] = e;
    g_ssrc[pos] = s;
    g_sdst[pos] = d;
}

// Layer-0 stats over sorted pairs (dst-sorted -> P rows L1-resident).
__global__ void k_stats0() {
    __shared__ float ss[CC], sq[CC];
    int t = threadIdx.x;
    if (t < CC) { ss[t] = 0.0f; sq[t] = 0.0f; }
    __syncthreads();
    int lane = t & 31;
    int warp = (blockIdx.x * 256 + t) >> 5;
    int nw = (gridDim.x * 256) >> 5;
    float2 s = make_float2(0.0f, 0.0f), q = make_float2(0.0f, 0.0f);
    for (int e = warp; e < EE; e += nw) {
        int dst = g_sdst[e], src = g_ssrc[e];
        float2 p = *(const float2*)&g_P[dst * CC + 2 * lane];
        float2 qq = *(const float2*)&g_Q[src * CC + 2 * lane];
        float y0 = p.x + qq.x, y1 = p.y + qq.y;
        s.x += y0; s.y += y1;
        q.x = fmaf(y0, y0, q.x); q.y = fmaf(y1, y1, q.y);
    }
    atomicAdd(&ss[2 * lane], s.x);
    atomicAdd(&ss[2 * lane + 1], s.y);
    atomicAdd(&sq[2 * lane], q.x);
    atomicAdd(&sq[2 * lane + 1], q.y);
    __syncthreads();
    if (t < CC) {
        atomicAdd(&g_sum[0][t], ss[t]);
        atomicAdd(&g_sq[0][t], sq[t]);
    }
}

__global__ void k_finalize(int layer, const float* __restrict__ gam,
                           const float* __restrict__ bet) {
    int c = threadIdx.x;
    float inv = 1.0f / (float)EE;
    float m = g_sum[layer][c] * inv;
    float v = g_sq[layer][c] * inv - m * m;
    float a = gam[c] * rsqrtf(v + BN_EPS);
    g_bnA[layer][c] = a;
    g_bnB[layer][c] = bet[c] - m * a;
}

// Prologue: bf16 hi/lo split of W1, W2 (row-major [k][n]).
__global__ void k_prepW(const float* __restrict__ W1, const float* __restrict__ W2) {
    const float* W = (blockIdx.x == 0) ? W1 : W2;
    for (int idx = threadIdx.x; idx < 4096; idx += 256) {
        float x = W[idx];
        __nv_bfloat16 hi = __float2bfloat16(x);
        __nv_bfloat16 lo = __float2bfloat16(x - __bfloat162float(hi));
        g_Whi[blockIdx.x][idx] = hi;
        g_Wlo[blockIdx.x][idx] = lo;
    }
}

// ---------------- WMMA edge layer: 256-edge tile, sorted-position order ----------------
// mode 0: A = BN0+ReLU(P[sdst]+Q[ssrc]), B = W1, g_Y[pos] = y1, stats -> 1
// mode 1: A = BN1+ReLU(g_Y[pos]),        B = W2, g_Y[pos] = y2, stats -> 2
// y = Ahi*Bhi + Alo*Bhi + Ahi*Blo (fp32 accum). Warp w owns rows [w*32,w*32+32)
// = two 16-row tiles; both tiles' accumulators stay live (8 frags) so stage
// (which aliases A) is written only after ALL A reads complete.
__global__ void __launch_bounds__(256, 2) k_layerT(int mode) {
    extern __shared__ char smem[];
    __nv_bfloat16* A_hi = (__nv_bfloat16*)(smem + O_AHI);
    __nv_bfloat16* A_lo = (__nv_bfloat16*)(smem + O_ALO);
    __nv_bfloat16* B_hi = (__nv_bfloat16*)(smem + O_BHI);
    __nv_bfloat16* B_lo = (__nv_bfloat16*)(smem + O_BLO);
    float* stage = (float*)smem;   // aliases A region after the post-GEMM barrier
    int t = threadIdx.x;

    // Prefetch gather indices first (starts the dependent chain early).
    int e0 = blockIdx.x * ROWS;
    int pos = e0 + t;              // thread t owns full row t
    const float* src0;
    const float* src1 = nullptr;
    int L;
    if (mode == 0) {
        int nd = g_sdst[pos];
        int ns = g_ssrc[pos];
        src0 = &g_P[(size_t)nd * CC];
        src1 = &g_Q[(size_t)ns * CC];
        L = 0;
    } else {
        src0 = &g_Y[(size_t)pos * CC];
        L = 1;
    }

    // copy W hi/lo into padded smem (row k -> B[k*LDB .. +64))
    {
        const uint32_t* wh = (const uint32_t*)&g_Whi[mode][0];
        const uint32_t* wl = (const uint32_t*)&g_Wlo[mode][0];
#pragma unroll
        for (int i = 0; i < 8; i++) {
            int idx2 = t + i * 256;
            int k = idx2 >> 5, n2 = idx2 & 31;
            ((uint32_t*)(B_hi + k * LDB))[n2] = wh[idx2];
            ((uint32_t*)(B_lo + k * LDB))[n2] = wl[idx2];
        }
    }

    // A fill: thread t = full row (64 cols), BN+ReLU+split -> bf16 hi/lo
#pragma unroll
    for (int i = 0; i < 8; i++) {
        int c = i * 8;
        float4 a0 = *(const float4*)&src0[c];
        float4 a1 = *(const float4*)&src0[c + 4];
        if (mode == 0) {
            float4 b0 = *(const float4*)&src1[c];
            float4 b1 = *(const float4*)&src1[c + 4];
            a0.x += b0.x; a0.y += b0.y; a0.z += b0.z; a0.w += b0.w;
            a1.x += b1.x; a1.y += b1.y; a1.z += b1.z; a1.w += b1.w;
        }
        float v[8] = {a0.x, a0.y, a0.z, a0.w, a1.x, a1.y, a1.z, a1.w};
        float4 A0 = *(const float4*)&g_bnA[L][c];
        float4 A1 = *(const float4*)&g_bnA[L][c + 4];
        float4 B0 = *(const float4*)&g_bnB[L][c];
        float4 B1 = *(const float4*)&g_bnB[L][c + 4];
        float bnA[8] = {A0.x, A0.y, A0.z, A0.w, A1.x, A1.y, A1.z, A1.w};
        float bnB[8] = {B0.x, B0.y, B0.z, B0.w, B1.x, B1.y, B1.z, B1.w};
        uint32_t hw[4], lw[4];
#pragma unroll
        for (int j = 0; j < 4; j++) {
            float x0 = fmaxf(fmaf(bnA[2 * j],     v[2 * j],     bnB[2 * j]),     0.0f);
            float x1 = fmaxf(fmaf(bnA[2 * j + 1], v[2 * j + 1], bnB[2 * j + 1]), 0.0f);
            __nv_bfloat16 h0 = __float2bfloat16(x0);
            __nv_bfloat16 h1 = __float2bfloat16(x1);
            __nv_bfloat16 l0 = __float2bfloat16(x0 - __bfloat162float(h0));
            __nv_bfloat16 l1 = __float2bfloat16(x1 - __bfloat162float(h1));
            hw[j] = (uint32_t)__bfloat16_as_ushort(h0) |
                    ((uint32_t)__bfloat16_as_ushort(h1) << 16);
            lw[j] = (uint32_t)__bfloat16_as_ushort(l0) |
                    ((uint32_t)__bfloat16_as_ushort(l1) << 16);
        }
        *(uint4*)&A_hi[t * LDA + c] = make_uint4(hw[0], hw[1], hw[2], hw[3]);
        *(uint4*)&A_lo[t * LDA + c] = make_uint4(lw[0], lw[1], lw[2], lw[3]);
    }
    __syncthreads();

    // WMMA: warp w -> two 16-row tiles, accumulators for BOTH tiles live.
    int w = t >> 5;
    wmma::fragment<wmma::accumulator, 16, 16, 16, float> acc0[4], acc1[4];
#pragma unroll
    for (int j = 0; j < 4; j++) {
        wmma::fill_fragment(acc0[j], 0.0f);
        wmma::fill_fragment(acc1[j], 0.0f);
    }
    int row0 = w * 32;
#pragma unroll
    for (int k0 = 0; k0 < 64; k0 += 16) {
        wmma::fragment<wmma::matrix_a, 16, 16, 16, __nv_bfloat16, wmma::row_major> ah0, al0, ah1, al1;
        wmma::load_matrix_sync(ah0, A_hi + row0 * LDA + k0, LDA);
        wmma::load_matrix_sync(al0, A_lo + row0 * LDA + k0, LDA);
        wmma::load_matrix_sync(ah1, A_hi + (row0 + 16) * LDA + k0, LDA);
        wmma::load_matrix_sync(al1, A_lo + (row0 + 16) * LDA + k0, LDA);
#pragma unroll
        for (int j = 0; j < 4; j++) {
            wmma::fragment<wmma::matrix_b, 16, 16, 16, __nv_bfloat16, wmma::row_major> bh, bl;
            wmma::load_matrix_sync(bh, B_hi + k0 * LDB + j * 16, LDB);
            wmma::load_matrix_sync(bl, B_lo + k0 * LDB + j * 16, LDB);
            wmma::mma_sync(acc0[j], ah0, bh, acc0[j]);
            wmma::mma_sync(acc0[j], al0, bh, acc0[j]);
            wmma::mma_sync(acc0[j], ah0, bl, acc0[j]);
            wmma::mma_sync(acc1[j], ah1, bh, acc1[j]);
            wmma::mma_sync(acc1[j], al1, bh, acc1[j]);
            wmma::mma_sync(acc1[j], ah1, bl, acc1[j]);
        }
    }
    __syncthreads();   // all warps done reading A before stage overwrite
#pragma unroll
    for (int j = 0; j < 4; j++) {
        wmma::store_matrix_sync(stage + row0 * LDS_F + j * 16, acc0[j], LDS_F,
                                wmma::mem_row_major);
        wmma::store_matrix_sync(stage + (row0 + 16) * LDS_F + j * 16, acc1[j], LDS_F,
                                wmma::mem_row_major);
    }
    __syncthreads();

    // column stats: 256 threads, c = t&63, quarter sums 64 rows
    int SL = (mode == 0) ? 1 : 2;
    {
        int c = t & 63, quarter = t >> 6;
        float s = 0.0f, q = 0.0f;
#pragma unroll 8
        for (int rr = 0; rr < 64; rr++) {
            float vv = stage[(quarter * 64 + rr) * LDS_F + c];
            s += vv;
            q = fmaf(vv, vv, q);
        }
        atomicAdd(&g_sum[SL][c], s);
        atomicAdd(&g_sq[SL][c], q);
    }

    // coalesced store of the 256x64 tile back to sorted scratch
    float* dst = g_Y + (size_t)e0 * CC;
#pragma unroll
    for (int j2 = 0; j2 < 16; j2++) {
        int f = j2 * 1024 + t * 4;
        int rr = f >> 6, cc2 = f & 63;
        uint4 v = *(const uint4*)&stage[rr * LDS_F + cc2];
        *(uint4*)&dst[f] = v;
    }
}

// Segmented mean: warp per node. Streams its CONTIGUOUS sorted g_Y segment
// (coalesced reads), applies BN2+ReLU, scatter-writes edge rows to outE in
// original order, accumulates and writes the node mean. No atomics.
__global__ void __launch_bounds__(256) k_agg(float* __restrict__ out) {
    int wid = (blockIdx.x * 256 + threadIdx.x) >> 5;
    int lane = threadIdx.x & 31;
    if (wid >= NN) return;
    int start = g_off[wid], end = g_off[wid + 1];
    float2 A = *(const float2*)&g_bnA[2][lane * 2];
    float2 Bv = *(const float2*)&g_bnB[2][lane * 2];
    float2 acc = make_float2(0.0f, 0.0f);
    float* oe = out + (size_t)NN * CC;
#pragma unroll 2
    for (int j = start; j < end; j++) {
        float2 v = *(const float2*)&g_Y[(size_t)j * CC + lane * 2];
        v.x = fmaxf(fmaf(A.x, v.x, Bv.x), 0.0f);
        v.y = fmaxf(fmaf(A.y, v.y, Bv.y), 0.0f);
        int eid = g_eperm[j];
        *(float2*)&oe[(size_t)eid * CC + lane * 2] = v;
        acc.x += v.x;
        acc.y += v.y;
    }
    float d = fmaxf((float)(end - start), 1.0f);
    *(float2*)&out[(size_t)wid * CC + lane * 2] =
        make_float2(acc.x / d, acc.y / d);
}

extern "C" void kernel_launch(void* const* d_in, const int* in_sizes, int n_in,
                              void* d_out, int out_size) {
    const float* x = (const float*)d_in[0];
    const void* ei = d_in[1];
    const float* W0 = (const float*)d_in[2];
    const float* g0 = (const float*)d_in[4];
    const float* be0 = (const float*)d_in[5];
    const float* W1 = (const float*)d_in[6];
    const float* g1 = (const float*)d_in[8];
    const float* be1 = (const float*)d_in[9];
    const float* W2 = (const float*)d_in[10];
    const float* g2 = (const float*)d_in[12];
    const float* be2 = (const float*)d_in[13];
    float* out = (float*)d_out;

    static int s_attr_done = 0;
    if (!s_attr_done) {
        cudaFuncSetAttribute(k_layerT, cudaFuncAttributeMaxDynamicSharedMemorySize, SMEM_LK);
        s_attr_done = 1;
    }

    k_zero<<<(NN + 255) / 256, 256>>>();
    k_detect<<<1, 256>>>((const unsigned*)ei);
    k_convert<<<(EE + 255) / 256, 256>>>(ei);
    k_node<<<(NN + 31) / 32, 256>>>(x, W0);
    k_scan<<<1, 1024>>>();
    k_sortE<<<(EE + 255) / 256, 256>>>();
    k_prepW<<<2, 256>>>(W1, W2);
    k_stats0<<<2048, 256>>>();
    k_finalize<<<1, 64>>>(0, g0, be0);
    k_layerT<<<EE / ROWS, 256, SMEM_LK>>>(0);
    k_finalize<<<1, 64>>>(1, g1, be1);
    k_layerT<<<EE / ROWS, 256, SMEM_LK>>>(1);
    k_finalize<<<1, 64>>>(2, g2, be2);
    k_agg<<<(NN * 32 + 255) / 256, 256>>>(out);
}

// round 15
// speedup vs baseline: 1.3053x; 1.0316x over previous
#include <cuda_runtime.h>
#include <cuda_bf16.h>
#include <mma.h>
#include <cstdint>

using namespace nvcuda;

#define NN 50000
#define EE 800000
#define CC 64
#define BN_EPS 1e-5f

#define NODE_BLOCKS 1563          // ceil(50000/32)

// ---------------- scratch (static __device__ globals; no allocation) ----------------
static __device__ __align__(16) float g_P[NN * CC];      // x @ W0[:64]
static __device__ __align__(16) float g_Q[NN * CC];      // x @ W0[64:]
static __device__ __align__(16) float g_Y[EE * CC];      // sorted-order y scratch
static __device__ int   g_src[EE];
static __device__ int   g_dst[EE];
static __device__ int   g_ssrc[EE];                      // src of sorted edge
static __device__ int   g_sdst[EE];                      // dst of sorted edge
static __device__ int   g_deg[NN];
static __device__ int   g_off[NN + 1];
static __device__ int   g_cur[NN];
static __device__ int   g_eperm[EE];                     // sorted pos -> original edge id
static __device__ __align__(16) float g_sum[3][CC];
static __device__ __align__(16) float g_sq[3][CC];
static __device__ int   g_is64;
// bf16 hi/lo split of W1/W2 (row-major [k][n])
static __device__ __align__(16) __nv_bfloat16 g_Whi[2][4096];
static __device__ __align__(16) __nv_bfloat16 g_Wlo[2][4096];

// ---------------- smem layout for wmma layer kernel (bytes) ----------------
// 256-edge tile: A_hi/A_lo 256x72 bf16, B_hi/B_lo 64x72 bf16, bn consts 512B.
// fp32 stage (256x68) aliases the A region after the GEMM barrier.
#define ROWS 256
#define LDA 72
#define LDB 72
#define LDS_F 68
#define O_AHI 0
#define O_ALO 36864     // 256*72*2
#define O_BHI 73728
#define O_BLO 82944
#define O_BN  92160     // 64 floats bnA + 64 floats bnB
#define SMEM_LK 92672

// ---------------- prologue kernels ----------------

// zero scratch; block 0 detects int64 vs int32; blocks 1,2 do the W hi/lo split.
__global__ void k_zero(const unsigned* __restrict__ w,
                       const float* __restrict__ W1,
                       const float* __restrict__ W2) {
    int i = blockIdx.x * 256 + threadIdx.x;
    if (i < NN) g_deg[i] = 0;
    if (i < 3 * CC) {
        ((float*)g_sum)[i] = 0.0f;
        ((float*)g_sq)[i] = 0.0f;
    }
    if (blockIdx.x == 0) {
        __shared__ int bad;
        if (threadIdx.x == 0) bad = 0;
        __syncthreads();
        int b = 0;
        for (int j = threadIdx.x; j < 1024; j += 256)
            if (w[2 * j + 1] != 0u) b = 1;
        if (b) atomicOr(&bad, 1);
        __syncthreads();
        if (threadIdx.x == 0) g_is64 = bad ? 0 : 1;
    } else if (blockIdx.x <= 2) {
        int which = blockIdx.x - 1;
        const float* W = (which == 0) ? W1 : W2;
        for (int idx = threadIdx.x; idx < 4096; idx += 256) {
            float v = W[idx];
            __nv_bfloat16 hi = __float2bfloat16(v);
            __nv_bfloat16 lo = __float2bfloat16(v - __bfloat162float(hi));
            g_Whi[which][idx] = hi;
            g_Wlo[which][idx] = lo;
        }
    }
}

__global__ void k_convert(const void* __restrict__ ei) {
    int e = blockIdx.x * 256 + threadIdx.x;
    if (e >= EE) return;
    int s, d;
    if (g_is64) {
        const long long* p = (const long long*)ei;
        s = (int)p[e];
        d = (int)p[EE + e];
    } else {
        const int* p = (const int*)ei;
        s = p[e];
        d = p[EE + e];
    }
    g_src[e] = s;
    g_dst[e] = d;
    atomicAdd(&g_deg[d], 1);
}

// Node-level GEMM: P = x @ W0[:64], Q = x @ W0[64:].
// Extra block (== NODE_BLOCKS) runs the degree scan, hidden under the GEMM wave.
__global__ void __launch_bounds__(256) k_node(const float* __restrict__ x,
                                              const float* __restrict__ W0) {
    __shared__ float sW[64][128];
    __shared__ float sx[32][64];
    int t = threadIdx.x;

    if (blockIdx.x == NODE_BLOCKS) {
        __shared__ int part[256];
        const int CH = (NN + 255) / 256;   // 196
        int base = t * CH;
        int s = 0;
        for (int j = 0; j < CH; j++) {
            int n = base + j;
            if (n < NN) s += g_deg[n];
        }
        part[t] = s;
        __syncthreads();
        for (int off = 1; off < 256; off <<= 1) {
            int v = (t >= off) ? part[t - off] : 0;
            __syncthreads();
            part[t] += v;
            __syncthreads();
        }
        int run = part[t] - s;
        for (int j = 0; j < CH; j++) {
            int n = base + j;
            if (n < NN) {
                g_off[n] = run;
                g_cur[n] = run;
                run += g_deg[n];
            }
        }
        if (t == 255) g_off[NN] = EE;
        return;
    }

#pragma unroll
    for (int i = 0; i < 32; i++) {
        int idx = t + i * 256;
        int k = idx >> 7;
        int cc = idx & 127;
        sW[k][cc] = (cc < 64) ? W0[k * 64 + cc] : W0[(64 + k) * 64 + (cc - 64)];
    }
    int n0 = blockIdx.x * 32;
#pragma unroll
    for (int i = 0; i < 8; i++) {
        int idx = t + i * 256;
        int nl = idx >> 6;
        int k = idx & 63;
        int n = n0 + nl;
        sx[nl][k] = (n < NN) ? x[n * 64 + k] : 0.0f;
    }
    __syncthreads();
    int tc = t & 31;
    int tn = t >> 5;
    float acc[4][4] = {};
#pragma unroll 16
    for (int k = 0; k < 64; k++) {
        float4 w = *(const float4*)&sW[k][tc * 4];
        float x0 = sx[tn * 4 + 0][k];
        float x1 = sx[tn * 4 + 1][k];
        float x2 = sx[tn * 4 + 2][k];
        float x3 = sx[tn * 4 + 3][k];
        acc[0][0] = fmaf(x0, w.x, acc[0][0]); acc[0][1] = fmaf(x0, w.y, acc[0][1]);
        acc[0][2] = fmaf(x0, w.z, acc[0][2]); acc[0][3] = fmaf(x0, w.w, acc[0][3]);
        acc[1][0] = fmaf(x1, w.x, acc[1][0]); acc[1][1] = fmaf(x1, w.y, acc[1][1]);
        acc[1][2] = fmaf(x1, w.z, acc[1][2]); acc[1][3] = fmaf(x1, w.w, acc[1][3]);
        acc[2][0] = fmaf(x2, w.x, acc[2][0]); acc[2][1] = fmaf(x2, w.y, acc[2][1]);
        acc[2][2] = fmaf(x2, w.z, acc[2][2]); acc[2][3] = fmaf(x2, w.w, acc[2][3]);
        acc[3][0] = fmaf(x3, w.x, acc[3][0]); acc[3][1] = fmaf(x3, w.y, acc[3][1]);
        acc[3][2] = fmaf(x3, w.z, acc[3][2]); acc[3][3] = fmaf(x3, w.w, acc[3][3]);
    }
#pragma unroll
    for (int i = 0; i < 4; i++) {
        int n = n0 + tn * 4 + i;
        if (n < NN) {
            float4 v = make_float4(acc[i][0], acc[i][1], acc[i][2], acc[i][3]);
            if (tc < 16)
                *(float4*)&g_P[n * 64 + tc * 4] = v;
            else
                *(float4*)&g_Q[n * 64 + (tc - 16) * 4] = v;
        }
    }
}

__global__ void k_sortE() {
    int e = blockIdx.x * 256 + threadIdx.x;
    if (e >= EE) return;
    int s = g_src[e];
    int d = g_dst[e];
    int pos = atomicAdd(&g_cur[d], 1);
    g_eperm[pos] = e;
    g_ssrc[pos] = s;
    g_sdst[pos] = d;
}

// Layer-0 stats over sorted pairs (dst-sorted -> P rows L1-resident).
__global__ void k_stats0() {
    __shared__ float ss[CC], sq[CC];
    int t = threadIdx.x;
    if (t < CC) { ss[t] = 0.0f; sq[t] = 0.0f; }
    __syncthreads();
    int lane = t & 31;
    int warp = (blockIdx.x * 256 + t) >> 5;
    int nw = (gridDim.x * 256) >> 5;
    float2 s = make_float2(0.0f, 0.0f), q = make_float2(0.0f, 0.0f);
    for (int e = warp; e < EE; e += nw) {
        int dst = g_sdst[e], src = g_ssrc[e];
        float2 p = *(const float2*)&g_P[dst * CC + 2 * lane];
        float2 qq = *(const float2*)&g_Q[src * CC + 2 * lane];
        float y0 = p.x + qq.x, y1 = p.y + qq.y;
        s.x += y0; s.y += y1;
        q.x = fmaf(y0, y0, q.x); q.y = fmaf(y1, y1, q.y);
    }
    atomicAdd(&ss[2 * lane], s.x);
    atomicAdd(&ss[2 * lane + 1], s.y);
    atomicAdd(&sq[2 * lane], q.x);
    atomicAdd(&sq[2 * lane + 1], q.y);
    __syncthreads();
    if (t < CC) {
        atomicAdd(&g_sum[0][t], ss[t]);
        atomicAdd(&g_sq[0][t], sq[t]);
    }
}

// ---------------- WMMA edge layer: 256-edge tile, sorted-position order ----------------
// mode 0: A = BN0+ReLU(P[sdst]+Q[ssrc]), B = W1, g_Y[pos] = y1, stats -> 1
// mode 1: A = BN1+ReLU(g_Y[pos]),        B = W2, g_Y[pos] = y2, stats -> 2
// BN constants for layer L computed PER BLOCK from g_sum/g_sq (finalize inlined).
// y = Ahi*Bhi + Alo*Bhi + Ahi*Blo (fp32 accum). Warp w owns rows [w*32,w*32+32)
// = two 16-row tiles; both tiles' accumulators stay live so stage (aliasing A)
// is written only after ALL A reads complete.
__global__ void __launch_bounds__(256, 2) k_layerT(int mode,
                                                   const float* __restrict__ gam,
                                                   const float* __restrict__ bet) {
    extern __shared__ char smem[];
    __nv_bfloat16* A_hi = (__nv_bfloat16*)(smem + O_AHI);
    __nv_bfloat16* A_lo = (__nv_bfloat16*)(smem + O_ALO);
    __nv_bfloat16* B_hi = (__nv_bfloat16*)(smem + O_BHI);
    __nv_bfloat16* B_lo = (__nv_bfloat16*)(smem + O_BLO);
    float* sBnA = (float*)(smem + O_BN);
    float* sBnB = sBnA + CC;
    float* stage = (float*)smem;   // aliases A region after the post-GEMM barrier
    int t = threadIdx.x;
    int L = mode;                  // BN layer index to APPLY (0 or 1)

    // inline finalize: 64 threads compute bnA/bnB for layer L
    if (t < CC) {
        float inv = 1.0f / (float)EE;
        float m = g_sum[L][t] * inv;
        float v = g_sq[L][t] * inv - m * m;
        float a = gam[t] * rsqrtf(v + BN_EPS);
        sBnA[t] = a;
        sBnB[t] = bet[t] - m * a;
    }

    // Prefetch gather indices (starts the dependent chain early).
    int e0 = blockIdx.x * ROWS;
    int pos = e0 + t;              // thread t owns full row t
    const float* src0;
    const float* src1 = nullptr;
    if (mode == 0) {
        int nd = g_sdst[pos];
        int ns = g_ssrc[pos];
        src0 = &g_P[(size_t)nd * CC];
        src1 = &g_Q[(size_t)ns * CC];
    } else {
        src0 = &g_Y[(size_t)pos * CC];
    }

    // copy W hi/lo into padded smem (row k -> B[k*LDB .. +64))
    {
        const uint32_t* wh = (const uint32_t*)&g_Whi[mode][0];
        const uint32_t* wl = (const uint32_t*)&g_Wlo[mode][0];
#pragma unroll
        for (int i = 0; i < 8; i++) {
            int idx2 = t + i * 256;
            int k = idx2 >> 5, n2 = idx2 & 31;
            ((uint32_t*)(B_hi + k * LDB))[n2] = wh[idx2];
            ((uint32_t*)(B_lo + k * LDB))[n2] = wl[idx2];
        }
    }
    __syncthreads();   // bn consts ready before A fill

    // A fill: thread t = full row (64 cols), BN+ReLU+split -> bf16 hi/lo
#pragma unroll
    for (int i = 0; i < 8; i++) {
        int c = i * 8;
        float4 a0 = *(const float4*)&src0[c];
        float4 a1 = *(const float4*)&src0[c + 4];
        if (mode == 0) {
            float4 b0 = *(const float4*)&src1[c];
            float4 b1 = *(const float4*)&src1[c + 4];
            a0.x += b0.x; a0.y += b0.y; a0.z += b0.z; a0.w += b0.w;
            a1.x += b1.x; a1.y += b1.y; a1.z += b1.z; a1.w += b1.w;
        }
        float v[8] = {a0.x, a0.y, a0.z, a0.w, a1.x, a1.y, a1.z, a1.w};
        float4 A0 = *(const float4*)&sBnA[c];
        float4 A1 = *(const float4*)&sBnA[c + 4];
        float4 B0 = *(const float4*)&sBnB[c];
        float4 B1 = *(const float4*)&sBnB[c + 4];
        float bnA[8] = {A0.x, A0.y, A0.z, A0.w, A1.x, A1.y, A1.z, A1.w};
        float bnB[8] = {B0.x, B0.y, B0.z, B0.w, B1.x, B1.y, B1.z, B1.w};
        uint32_t hw[4], lw[4];
#pragma unroll
        for (int j = 0; j < 4; j++) {
            float x0 = fmaxf(fmaf(bnA[2 * j],     v[2 * j],     bnB[2 * j]),     0.0f);
            float x1 = fmaxf(fmaf(bnA[2 * j + 1], v[2 * j + 1], bnB[2 * j + 1]), 0.0f);
            __nv_bfloat16 h0 = __float2bfloat16(x0);
            __nv_bfloat16 h1 = __float2bfloat16(x1);
            __nv_bfloat16 l0 = __float2bfloat16(x0 - __bfloat162float(h0));
            __nv_bfloat16 l1 = __float2bfloat16(x1 - __bfloat162float(h1));
            hw[j] = (uint32_t)__bfloat16_as_ushort(h0) |
                    ((uint32_t)__bfloat16_as_ushort(h1) << 16);
            lw[j] = (uint32_t)__bfloat16_as_ushort(l0) |
                    ((uint32_t)__bfloat16_as_ushort(l1) << 16);
        }
        *(uint4*)&A_hi[t * LDA + c] = make_uint4(hw[0], hw[1], hw[2], hw[3]);
        *(uint4*)&A_lo[t * LDA + c] = make_uint4(lw[0], lw[1], lw[2], lw[3]);
    }
    __syncthreads();

    // WMMA: warp w -> two 16-row tiles, accumulators for BOTH tiles live.
    int w = t >> 5;
    wmma::fragment<wmma::accumulator, 16, 16, 16, float> acc0[4], acc1[4];
#pragma unroll
    for (int j = 0; j < 4; j++) {
        wmma::fill_fragment(acc0[j], 0.0f);
        wmma::fill_fragment(acc1[j], 0.0f);
    }
    int row0 = w * 32;
#pragma unroll
    for (int k0 = 0; k0 < 64; k0 += 16) {
        wmma::fragment<wmma::matrix_a, 16, 16, 16, __nv_bfloat16, wmma::row_major> ah0, al0, ah1, al1;
        wmma::load_matrix_sync(ah0, A_hi + row0 * LDA + k0, LDA);
        wmma::load_matrix_sync(al0, A_lo + row0 * LDA + k0, LDA);
        wmma::load_matrix_sync(ah1, A_hi + (row0 + 16) * LDA + k0, LDA);
        wmma::load_matrix_sync(al1, A_lo + (row0 + 16) * LDA + k0, LDA);
#pragma unroll
        for (int j = 0; j < 4; j++) {
            wmma::fragment<wmma::matrix_b, 16, 16, 16, __nv_bfloat16, wmma::row_major> bh, bl;
            wmma::load_matrix_sync(bh, B_hi + k0 * LDB + j * 16, LDB);
            wmma::load_matrix_sync(bl, B_lo + k0 * LDB + j * 16, LDB);
            wmma::mma_sync(acc0[j], ah0, bh, acc0[j]);
            wmma::mma_sync(acc0[j], al0, bh, acc0[j]);
            wmma::mma_sync(acc0[j], ah0, bl, acc0[j]);
            wmma::mma_sync(acc1[j], ah1, bh, acc1[j]);
            wmma::mma_sync(acc1[j], al1, bh, acc1[j]);
            wmma::mma_sync(acc1[j], ah1, bl, acc1[j]);
        }
    }
    __syncthreads();   // all warps done reading A before stage overwrite
#pragma unroll
    for (int j = 0; j < 4; j++) {
        wmma::store_matrix_sync(stage + row0 * LDS_F + j * 16, acc0[j], LDS_F,
                                wmma::mem_row_major);
        wmma::store_matrix_sync(stage + (row0 + 16) * LDS_F + j * 16, acc1[j], LDS_F,
                                wmma::mem_row_major);
    }
    __syncthreads();

    // column stats: 256 threads, c = t&63, quarter sums 64 rows
    int SL = (mode == 0) ? 1 : 2;
    {
        int c = t & 63, quarter = t >> 6;
        float s = 0.0f, q = 0.0f;
#pragma unroll 8
        for (int rr = 0; rr < 64; rr++) {
            float vv = stage[(quarter * 64 + rr) * LDS_F + c];
            s += vv;
            q = fmaf(vv, vv, q);
        }
        atomicAdd(&g_sum[SL][c], s);
        atomicAdd(&g_sq[SL][c], q);
    }

    // coalesced store of the 256x64 tile back to sorted scratch
    float* dst = g_Y + (size_t)e0 * CC;
#pragma unroll
    for (int j2 = 0; j2 < 16; j2++) {
        int f = j2 * 1024 + t * 4;
        int rr = f >> 6, cc2 = f & 63;
        uint4 v = *(const uint4*)&stage[rr * LDS_F + cc2];
        *(uint4*)&dst[f] = v;
    }
}

// Segmented mean: warp per node. BN2 constants computed per-thread (finalize
// inlined). Streams its CONTIGUOUS sorted g_Y segment, applies BN2+ReLU,
// scatter-writes edge rows to outE in original order, writes the node mean.
__global__ void __launch_bounds__(256) k_agg(float* __restrict__ out,
                                             const float* __restrict__ gam,
                                             const float* __restrict__ bet) {
    int wid = (blockIdx.x * 256 + threadIdx.x) >> 5;
    int lane = threadIdx.x & 31;
    if (wid >= NN) return;
    int start = g_off[wid], end = g_off[wid + 1];
    int c0 = lane * 2, c1 = lane * 2 + 1;
    float inv = 1.0f / (float)EE;
    float m0 = g_sum[2][c0] * inv, m1 = g_sum[2][c1] * inv;
    float v0 = g_sq[2][c0] * inv - m0 * m0;
    float v1 = g_sq[2][c1] * inv - m1 * m1;
    float2 A, Bv;
    A.x = gam[c0] * rsqrtf(v0 + BN_EPS);
    A.y = gam[c1] * rsqrtf(v1 + BN_EPS);
    Bv.x = bet[c0] - m0 * A.x;
    Bv.y = bet[c1] - m1 * A.y;
    float2 acc = make_float2(0.0f, 0.0f);
    float* oe = out + (size_t)NN * CC;
#pragma unroll 2
    for (int j = start; j < end; j++) {
        float2 v = *(const float2*)&g_Y[(size_t)j * CC + lane * 2];
        v.x = fmaxf(fmaf(A.x, v.x, Bv.x), 0.0f);
        v.y = fmaxf(fmaf(A.y, v.y, Bv.y), 0.0f);
        int eid = g_eperm[j];
        *(float2*)&oe[(size_t)eid * CC + lane * 2] = v;
        acc.x += v.x;
        acc.y += v.y;
    }
    float d = fmaxf((float)(end - start), 1.0f);
    *(float2*)&out[(size_t)wid * CC + lane * 2] =
        make_float2(acc.x / d, acc.y / d);
}

extern "C" void kernel_launch(void* const* d_in, const int* in_sizes, int n_in,
                              void* d_out, int out_size) {
    const float* x = (const float*)d_in[0];
    const void* ei = d_in[1];
    const float* W0 = (const float*)d_in[2];
    const float* g0 = (const float*)d_in[4];
    const float* be0 = (const float*)d_in[5];
    const float* W1 = (const float*)d_in[6];
    const float* g1 = (const float*)d_in[8];
    const float* be1 = (const float*)d_in[9];
    const float* W2 = (const float*)d_in[10];
    const float* g2 = (const float*)d_in[12];
    const float* be2 = (const float*)d_in[13];
    float* out = (float*)d_out;

    static int s_attr_done = 0;
    if (!s_attr_done) {
        cudaFuncSetAttribute(k_layerT, cudaFuncAttributeMaxDynamicSharedMemorySize, SMEM_LK);
        s_attr_done = 1;
    }

    k_zero<<<(NN + 255) / 256, 256>>>((const unsigned*)ei, W1, W2);
    k_convert<<<(EE + 255) / 256, 256>>>(ei);
    k_node<<<NODE_BLOCKS + 1, 256>>>(x, W0);
    k_sortE<<<(EE + 255) / 256, 256>>>();
    k_stats0<<<2048, 256>>>();
    k_layerT<<<EE / ROWS, 256, SMEM_LK>>>(0, g0, be0);
    k_layerT<<<EE / ROWS, 256, SMEM_LK>>>(1, g1, be1);
    k_agg<<<(NN * 32 + 255) / 256, 256>>>(out, g2, be2);
}